// round 2
// baseline (speedup 1.0000x reference)
#include <cuda_runtime.h>

// MinimalRNN: 3-layer tanh RNN, S=256, B=256, H=1024.
// Persistent cooperative kernel, skewed layer pipeline (layer l computes
// timestep t = s - l at global step s), one grid barrier per global step.
// fp32 compute via packed fma.rn.f32x2 (2 MACs / instruction).

#define S_LEN   256
#define BATCH   256
#define HID     1024
#define NLAYER  3
#define NT      16                 // output columns per CTA
#define TPL     (HID / NT)         // 64 tiles per layer
#define NCTA    (NLAYER * TPL)     // 192
#define NTHREADS 256
#define KC      32                 // K-chunk staged in SMEM
#define ASTR    (KC + 4)           // 36 floats: A-tile row stride (pad)
#define WSTR    (NT + 4)           // 20 floats: W-tile row stride (pad)

#define Y_ELEMS ((size_t)S_LEN * BATCH * HID)

// Double-buffered hidden state: parity = global step s & 1.
__device__ __align__(16) float g_hbuf[2][NLAYER][BATCH][HID];
__device__ unsigned g_count = 0;
__device__ unsigned g_gen   = 0;

__device__ __forceinline__ unsigned ld_acq(const unsigned* p) {
    unsigned v;
    asm volatile("ld.acquire.gpu.global.u32 %0, [%1];" : "=r"(v) : "l"(p) : "memory");
    return v;
}

__device__ __forceinline__ void grid_barrier() {
    __syncthreads();
    if (threadIdx.x == 0) {
        __threadfence();
        unsigned gen = ld_acq(&g_gen);     // read BEFORE arriving
        __threadfence();
        unsigned ticket = atomicAdd(&g_count, 1u);
        if (ticket == NCTA - 1) {
            atomicExch(&g_count, 0u);      // reset before release
            __threadfence();
            atomicAdd(&g_gen, 1u);
        } else {
            while (ld_acq(&g_gen) == gen) { __nanosleep(64); }
        }
        __threadfence();
    }
    __syncthreads();
}

// ---- packed f32x2 helpers ----
__device__ __forceinline__ void ffma2(unsigned long long& d,
                                      unsigned long long a,
                                      unsigned long long b) {
    asm volatile("fma.rn.f32x2 %0, %1, %2, %0;" : "+l"(d) : "l"(a), "l"(b));
}
__device__ __forceinline__ unsigned long long splat2(float v) {
    unsigned long long r;
    asm("mov.b64 %0, {%1, %1};" : "=l"(r) : "f"(v));
    return r;
}
__device__ __forceinline__ unsigned long long pack2(float a, float b) {
    unsigned long long r;
    asm("mov.b64 %0, {%1, %2};" : "=l"(r) : "f"(a), "f"(b));
    return r;
}
__device__ __forceinline__ float2 unpack2(unsigned long long v) {
    float2 f;
    asm("mov.b64 {%0, %1}, %2;" : "=f"(f.x), "=f"(f.y) : "l"(v));
    return f;
}

// Accumulate acc[4 rows][2 col-pairs] += A[256 x 1024] * W[n0..n0+15][1024]^T
// A rows r = ty + 64*ri, cols c = n0 + tx*4 + {0..3}.
__device__ __forceinline__ void gemm_acc(
    const float* __restrict__ A,   // [BATCH][HID] activations (L1-bypassed reads)
    const float* __restrict__ W,   // [HID][HID] weight matrix (row-major, row = out col)
    int n0, int tid, int ty, int tx,
    unsigned long long acc[4][2],
    float At[BATCH][ASTR], float Wt[KC][WSTR])
{
    const int arow = tid >> 3;     // 0..31
    const int aq   = tid & 7;      // 0..7 : float4 index within KC
    const int wc   = tid & 15;     // weight col within tile
    const int wq   = tid >> 4;     // 0..7 when tid < 128

    for (int kc = 0; kc < HID; kc += KC) {
        // stage A chunk [256 x KC]: 8 lanes cover one row's 128B -> coalesced
        #pragma unroll
        for (int it = 0; it < 8; it++) {
            int row = arow + 32 * it;
            float4 v = __ldcg((const float4*)(A + (size_t)row * HID + kc + aq * 4));
            *(float4*)&At[row][aq * 4] = v;
        }
        // stage W chunk transposed: Wt[kk][c] = W[n0+c][kc+kk]
        if (tid < 128) {
            float4 wv = __ldg((const float4*)(W + (size_t)(n0 + wc) * HID + kc + wq * 4));
            Wt[wq * 4 + 0][wc] = wv.x;
            Wt[wq * 4 + 1][wc] = wv.y;
            Wt[wq * 4 + 2][wc] = wv.z;
            Wt[wq * 4 + 3][wc] = wv.w;
        }
        __syncthreads();

        #pragma unroll
        for (int k4 = 0; k4 < KC; k4 += 4) {
            ulonglong2 wp[4];                     // wp[j] = W cols (c0,c1),(c2,c3) at k4+j
            #pragma unroll
            for (int j = 0; j < 4; j++)
                wp[j] = *(const ulonglong2*)&Wt[k4 + j][tx * 4];
            float4 av[4];                         // av[ri] = A[row_ri][k4..k4+3]
            #pragma unroll
            for (int ri = 0; ri < 4; ri++)
                av[ri] = *(const float4*)&At[ty + 64 * ri][k4];
            #pragma unroll
            for (int j = 0; j < 4; j++) {
                #pragma unroll
                for (int ri = 0; ri < 4; ri++) {
                    float a = ((const float*)&av[ri])[j];
                    unsigned long long as = splat2(a);
                    ffma2(acc[ri][0], as, wp[j].x);
                    ffma2(acc[ri][1], as, wp[j].y);
                }
            }
        }
        __syncthreads();
    }
}

extern "C" __global__ void __launch_bounds__(NTHREADS, 2)
rnn_persistent(const float* __restrict__ x,   // [S][B][H]
               const float* __restrict__ h0,  // [L][B][H]
               const float* __restrict__ Wih, // [L][H][H]
               const float* __restrict__ Whh, // [L][H][H]
               const float* __restrict__ bih, // [L][H]
               const float* __restrict__ bhh, // [L][H]
               float* __restrict__ out)       // [S*B*H + L*B*H]
{
    __shared__ float At[BATCH][ASTR];
    __shared__ float Wt[KC][WSTR];

    const int tid = threadIdx.x;
    const int ty  = tid >> 2;      // 0..63 : batch-row group
    const int tx  = tid & 3;       // 0..3  : col group (4 cols each)
    const int l   = blockIdx.x / TPL;
    const int n0  = (blockIdx.x % TPL) * NT;

    const float* Wl_ih = Wih + (size_t)l * HID * HID;
    const float* Wl_hh = Whh + (size_t)l * HID * HID;

    float bias[4];
    #pragma unroll
    for (int j = 0; j < 4; j++) {
        int c = n0 + tx * 4 + j;
        bias[j] = __ldg(&bih[l * HID + c]) + __ldg(&bhh[l * HID + c]);
    }

    for (int s = 0; s < S_LEN + NLAYER - 1; s++) {
        if (s > 0) grid_barrier();
        int t = s - l;                       // timestep for this layer at this step
        if (t < 0 || t >= S_LEN) continue;   // uniform per CTA

        unsigned long long acc[4][2];
        #pragma unroll
        for (int ri = 0; ri < 4; ri++) {
            acc[ri][0] = pack2(bias[0], bias[1]);
            acc[ri][1] = pack2(bias[2], bias[3]);
        }

        // feed-forward input: x_t for layer 0, else previous layer's output (prev parity)
        const float* A0 = (l == 0) ? (x + (size_t)t * BATCH * HID)
                                   : &g_hbuf[(s + 1) & 1][l - 1][0][0];
        // recurrent input: h_0 at t==0, else own output from previous step (prev parity)
        const float* A1 = (t == 0) ? (h0 + (size_t)l * BATCH * HID)
                                   : &g_hbuf[(s + 1) & 1][l][0][0];

        gemm_acc(A0, Wl_ih, n0, tid, ty, tx, acc, At, Wt);
        gemm_acc(A1, Wl_hh, n0, tid, ty, tx, acc, At, Wt);

        float* hb = &g_hbuf[s & 1][l][0][0];
        #pragma unroll
        for (int ri = 0; ri < 4; ri++) {
            float2 v0 = unpack2(acc[ri][0]);
            float2 v1 = unpack2(acc[ri][1]);
            float4 h;
            h.x = tanhf(v0.x); h.y = tanhf(v0.y);
            h.z = tanhf(v1.x); h.w = tanhf(v1.y);
            int row = ty + 64 * ri;
            size_t off = (size_t)row * HID + n0 + tx * 4;
            *(float4*)(hb + off) = h;
            if (l == NLAYER - 1)             // y output
                *(float4*)(out + (size_t)t * BATCH * HID + off) = h;
            if (t == S_LEN - 1)              // final hidden state h_N
                *(float4*)(out + Y_ELEMS + (size_t)l * BATCH * HID + off) = h;
        }
    }
}

extern "C" void kernel_launch(void* const* d_in, const int* in_sizes, int n_in,
                              void* d_out, int out_size) {
    const float* x   = (const float*)d_in[0];
    const float* h0  = (const float*)d_in[1];
    const float* Wih = (const float*)d_in[2];
    const float* Whh = (const float*)d_in[3];
    const float* bih = (const float*)d_in[4];
    const float* bhh = (const float*)d_in[5];
    rnn_persistent<<<NCTA, NTHREADS>>>(x, h0, Wih, Whh, bih, bhh, (float*)d_out);
}